// round 8
// baseline (speedup 1.0000x reference)
#include <cuda_runtime.h>
#include <cuda_bf16.h>

// y[b,c,h,w] = coef[c] * g[b,c,h,w]
// g: (32, 512, 64, 64) fp32, coef: (512,) fp32.
//
// PERSISTENT single-wave kernel: grid = 148 SMs x 8 CTAs = 1184 blocks,
// 256 threads each (2048 thr/SM). Each CTA grid-strides over the 16384
// channel planes (~14 planes per CTA), eliminating the 13 wave transitions
// of the one-plane-per-block launch and keeping a continuous DRAM stream
// (next plane's loads overlap previous plane's store drain).
//
// Per-plane body = proven R4 optimum: 4x front-batched LDG.128 (.cs evict-
// first, zero-reuse stream), block-uniform coef (c = plane & 511), 4x STG.128.

#define NPLANES   16384
#define GRID_PERS 1184

__global__ __launch_bounds__(256)
void Gradient_28733331210651_kernel(const float4* __restrict__ g4,
                                    const float* __restrict__ coef,
                                    float4* __restrict__ out4) {
    const unsigned t = threadIdx.x;

    for (unsigned p = blockIdx.x; p < NPLANES; p += GRID_PERS) {
        const float s = __ldg(coef + (p & 511));
        const long long base = (long long)p * 1024 + t;

        float4 v0 = __ldcs(g4 + base);
        float4 v1 = __ldcs(g4 + base + 256);
        float4 v2 = __ldcs(g4 + base + 512);
        float4 v3 = __ldcs(g4 + base + 768);

        v0.x *= s; v0.y *= s; v0.z *= s; v0.w *= s;
        v1.x *= s; v1.y *= s; v1.z *= s; v1.w *= s;
        v2.x *= s; v2.y *= s; v2.z *= s; v2.w *= s;
        v3.x *= s; v3.y *= s; v3.z *= s; v3.w *= s;

        __stcs(out4 + base,       v0);
        __stcs(out4 + base + 256, v1);
        __stcs(out4 + base + 512, v2);
        __stcs(out4 + base + 768, v3);
    }
}

extern "C" void kernel_launch(void* const* d_in, const int* in_sizes, int n_in,
                              void* d_out, int out_size) {
    const float4* g4   = (const float4*)d_in[0];
    const float*  coef = (const float*)d_in[1];
    float4*       out4 = (float4*)d_out;

    (void)in_sizes; (void)n_in; (void)out_size;
    Gradient_28733331210651_kernel<<<GRID_PERS, 256>>>(g4, coef, out4);
}

// round 9
// speedup vs baseline: 1.1214x; 1.1214x over previous
#include <cuda_runtime.h>
#include <cuda_bf16.h>

// y[b,c,h,w] = coef[c] * g[b,c,h,w]
// g: (32, 512, 64, 64) fp32, coef: (512,) fp32.
//
// One block = 512 threads x 4 float4 = 8192 floats = TWO consecutive (b,c)
// channel planes. Grid = 32*512/2 = 8192 blocks. Per-thread shape identical
// to the best measured config (R4: ILP=4 front-batched LDG.128.cs, 16 data
// regs): loads at tid + {0,512,1024,1536} float4.
//   tiles [0,1024)    = plane c0 -> loads 0,1 scaled by s0
//   tiles [1024,2048) = plane c0+1 -> loads 2,3 scaled by s1
// Both scales block-uniform: c0 = (2*blockIdx.x) & 511.
// .cs (evict-first) on loads+stores: zero-reuse 512 MiB stream.

__global__ __launch_bounds__(512)
void Gradient_28733331210651_kernel(const float4* __restrict__ g4,
                                    const float* __restrict__ coef,
                                    float4* __restrict__ out4) {
    const int c0 = (blockIdx.x << 1) & 511;
    const float s0 = __ldg(coef + c0);
    const float s1 = __ldg(coef + c0 + 1);

    const long long base = (long long)blockIdx.x * 2048 + threadIdx.x;

    // Front-batched loads (MLP=4 per thread)
    float4 v0 = __ldcs(g4 + base);           // plane c0
    float4 v1 = __ldcs(g4 + base + 512);     // plane c0
    float4 v2 = __ldcs(g4 + base + 1024);    // plane c0+1
    float4 v3 = __ldcs(g4 + base + 1536);    // plane c0+1

    v0.x *= s0; v0.y *= s0; v0.z *= s0; v0.w *= s0;
    v1.x *= s0; v1.y *= s0; v1.z *= s0; v1.w *= s0;
    v2.x *= s1; v2.y *= s1; v2.z *= s1; v2.w *= s1;
    v3.x *= s1; v3.y *= s1; v3.z *= s1; v3.w *= s1;

    __stcs(out4 + base,        v0);
    __stcs(out4 + base + 512,  v1);
    __stcs(out4 + base + 1024, v2);
    __stcs(out4 + base + 1536, v3);
}

extern "C" void kernel_launch(void* const* d_in, const int* in_sizes, int n_in,
                              void* d_out, int out_size) {
    const float4* g4   = (const float4*)d_in[0];
    const float*  coef = (const float*)d_in[1];
    float4*       out4 = (float4*)d_out;

    // 32*512*64*64 floats; one block per 8192-float pair of channel planes
    long long n  = (long long)in_sizes[0];      // 67108864
    long long blocks = n >> 13;                 // 8192

    Gradient_28733331210651_kernel<<<(unsigned)blocks, 512>>>(g4, coef, out4);
}